// round 1
// baseline (speedup 1.0000x reference)
#include <cuda_runtime.h>

#define NN 50000
#define DD 128
#define EE 1600000
#define TWO_N (2*NN)
#define SCAN_B 512
#define NSB ((TWO_N + SCAN_B - 1)/SCAN_B)
#define TILE_R 64
#define NBLK ((NN + TILE_R - 1)/TILE_R)

// ---------------- scratch (static device allocations) ----------------
__device__ int   g_cnt[TWO_N];        // degree, then fill-cursor
__device__ int   g_off[TWO_N + 1];    // CSR row offsets (set A rows 0..N-1, set B rows N..2N-1)
__device__ int   g_bsum[NSB];
__device__ int   g_col[2*EE];         // CSR column (src) indices
__device__ float g_ua[NN*DD];         // t + sum_{e_t} t[src]
__device__ float g_ub[NN*DD];         // t + sum_{e_xct} x[src]
__device__ float g_ga[NN*DD];         // gin_a output
__device__ float g_t2[NN*DD];         // relu(t + gin_a + gin_b)

// ---------------- CSR construction ----------------
__global__ void zero_cnt_kernel() {
    int i = blockIdx.x*blockDim.x + threadIdx.x;
    if (i < TWO_N) g_cnt[i] = 0;
}

__global__ void hist_kernel(const int* __restrict__ et, const int* __restrict__ ex) {
    int i = blockIdx.x*blockDim.x + threadIdx.x;
    if (i < EE) {
        atomicAdd(&g_cnt[et[EE + i]], 1);          // e_t dst
        atomicAdd(&g_cnt[NN + ex[EE + i]], 1);     // e_xct dst
    }
}

__global__ void scan1_kernel() {
    __shared__ int s[SCAN_B];
    int i = blockIdx.x*SCAN_B + threadIdx.x;
    int v = (i < TWO_N) ? g_cnt[i] : 0;
    s[threadIdx.x] = v;
    __syncthreads();
    #pragma unroll
    for (int d = 1; d < SCAN_B; d <<= 1) {
        int tv = (threadIdx.x >= d) ? s[threadIdx.x - d] : 0;
        __syncthreads();
        s[threadIdx.x] += tv;
        __syncthreads();
    }
    if (i < TWO_N) g_off[i + 1] = s[threadIdx.x];
    if (threadIdx.x == SCAN_B - 1) g_bsum[blockIdx.x] = s[SCAN_B - 1];
}

__global__ void scan2_kernel() {
    if (threadIdx.x == 0) {
        int run = 0;
        for (int b = 0; b < NSB; b++) { int t = g_bsum[b]; g_bsum[b] = run; run += t; }
    }
}

__global__ void scan3_kernel() {
    int i = blockIdx.x*blockDim.x + threadIdx.x;
    if (i == 0) { g_off[0] = 0; g_cnt[0] = 0; }
    else if (i <= TWO_N) {
        int v = g_off[i] + g_bsum[(i - 1) / SCAN_B];
        g_off[i] = v;
        if (i < TWO_N) g_cnt[i] = v;   // cursor = row start
    }
}

__global__ void fill_kernel(const int* __restrict__ et, const int* __restrict__ ex) {
    int i = blockIdx.x*blockDim.x + threadIdx.x;
    if (i < EE) {
        int p = atomicAdd(&g_cnt[et[EE + i]], 1);
        g_col[p] = et[i];
        int q = atomicAdd(&g_cnt[NN + ex[EE + i]], 1);
        g_col[q] = ex[i];
    }
}

// ---------------- aggregation: warp per destination node ----------------
__global__ void agg_kernel(const float* __restrict__ x, const float* __restrict__ t,
                           float* __restrict__ ua, float* __restrict__ ub) {
    int warp = (blockIdx.x*blockDim.x + threadIdx.x) >> 5;
    int lane = threadIdx.x & 31;
    if (warp >= NN) return;
    const float4* t4 = (const float4*)t;
    const float4* x4 = (const float4*)x;

    float4 base = t4[warp*32 + lane];
    float4 aA = base, aB = base;

    int e  = g_off[warp],      eE = g_off[warp + 1];
    for (; e + 1 < eE; e += 2) {
        int s0 = g_col[e], s1 = g_col[e + 1];
        float4 v0 = t4[s0*32 + lane];
        float4 v1 = t4[s1*32 + lane];
        aA.x += v0.x; aA.y += v0.y; aA.z += v0.z; aA.w += v0.w;
        aA.x += v1.x; aA.y += v1.y; aA.z += v1.z; aA.w += v1.w;
    }
    if (e < eE) {
        int s0 = g_col[e];
        float4 v0 = t4[s0*32 + lane];
        aA.x += v0.x; aA.y += v0.y; aA.z += v0.z; aA.w += v0.w;
    }

    e = g_off[NN + warp]; eE = g_off[NN + warp + 1];
    for (; e + 1 < eE; e += 2) {
        int s0 = g_col[e], s1 = g_col[e + 1];
        float4 v0 = x4[s0*32 + lane];
        float4 v1 = x4[s1*32 + lane];
        aB.x += v0.x; aB.y += v0.y; aB.z += v0.z; aB.w += v0.w;
        aB.x += v1.x; aB.y += v1.y; aB.z += v1.z; aB.w += v1.w;
    }
    if (e < eE) {
        int s0 = g_col[e];
        float4 v0 = x4[s0*32 + lane];
        aB.x += v0.x; aB.y += v0.y; aB.z += v0.z; aB.w += v0.w;
    }

    ((float4*)ua)[warp*32 + lane] = aA;
    ((float4*)ub)[warp*32 + lane] = aB;
}

// ---------------- fused 2-layer MLP (both weights resident in smem) ----------------
// MODE 0: OUT = A@W1(relu)@W2 + b2                     (gin_a)
// MODE 1: OUT = relu(R1 + R2 + mlp(A))                 (t2 from gin_b)
// MODE 3: OUT = A + mlp(A)                             (fc_x branch, residual from smem tile)
#define SMEM_MLP_FLOATS (16384 + 16384 + 8320 + 8320 + 128 + 128)
#define SMEM_MLP_BYTES  (SMEM_MLP_FLOATS * 4)

template<int MODE>
__global__ __launch_bounds__(256, 1) void mlp_kernel(
    const float* __restrict__ A,
    const float* __restrict__ W1, const float* __restrict__ B1,
    const float* __restrict__ W2, const float* __restrict__ B2,
    const float* __restrict__ R1, const float* __restrict__ R2,
    float* __restrict__ OUT)
{
    extern __shared__ float sm[];
    float* sW1 = sm;
    float* sW2 = sm + 16384;
    float* sAT = sm + 32768;        // [128][65] transposed, padded
    float* sHT = sAT + 8320;        // [128][65]
    float* sB1 = sHT + 8320;
    float* sB2 = sB1 + 128;

    const int tid = threadIdx.x;
    for (int i = tid; i < 16384; i += 256) { sW1[i] = W1[i]; sW2[i] = W2[i]; }
    if (tid < 128) { sB1[tid] = B1[tid]; sB2[tid] = B2[tid]; }

    const int row0 = blockIdx.x * TILE_R;
    for (int idx = tid; idx < TILE_R*128; idx += 256) {
        int r = idx >> 7, k = idx & 127;
        int row = row0 + r;
        sAT[k*65 + r] = (row < NN) ? A[(size_t)row*128 + k] : 0.f;
    }
    __syncthreads();

    const int tc = tid & 31;          // col group: cols tc*4..tc*4+3
    const int rb = (tid >> 5) * 8;    // row base within tile

    float acc[8][4];
    #pragma unroll
    for (int i = 0; i < 8; i++)
        #pragma unroll
        for (int j = 0; j < 4; j++) acc[i][j] = 0.f;

    #pragma unroll 4
    for (int k = 0; k < 128; k++) {
        const float* ap = &sAT[k*65 + rb];
        float4 bv = *(const float4*)(sW1 + k*128 + tc*4);
        #pragma unroll
        for (int i = 0; i < 8; i++) {
            float a = ap[i];
            acc[i][0] = fmaf(a, bv.x, acc[i][0]);
            acc[i][1] = fmaf(a, bv.y, acc[i][1]);
            acc[i][2] = fmaf(a, bv.z, acc[i][2]);
            acc[i][3] = fmaf(a, bv.w, acc[i][3]);
        }
    }

    {   // bias + relu -> transposed H tile
        float4 b1v = *(const float4*)(sB1 + tc*4);
        #pragma unroll
        for (int i = 0; i < 8; i++) {
            sHT[(tc*4 + 0)*65 + rb + i] = fmaxf(acc[i][0] + b1v.x, 0.f);
            sHT[(tc*4 + 1)*65 + rb + i] = fmaxf(acc[i][1] + b1v.y, 0.f);
            sHT[(tc*4 + 2)*65 + rb + i] = fmaxf(acc[i][2] + b1v.z, 0.f);
            sHT[(tc*4 + 3)*65 + rb + i] = fmaxf(acc[i][3] + b1v.w, 0.f);
        }
    }
    __syncthreads();

    #pragma unroll
    for (int i = 0; i < 8; i++)
        #pragma unroll
        for (int j = 0; j < 4; j++) acc[i][j] = 0.f;

    #pragma unroll 4
    for (int k = 0; k < 128; k++) {
        const float* ap = &sHT[k*65 + rb];
        float4 bv = *(const float4*)(sW2 + k*128 + tc*4);
        #pragma unroll
        for (int i = 0; i < 8; i++) {
            float a = ap[i];
            acc[i][0] = fmaf(a, bv.x, acc[i][0]);
            acc[i][1] = fmaf(a, bv.y, acc[i][1]);
            acc[i][2] = fmaf(a, bv.z, acc[i][2]);
            acc[i][3] = fmaf(a, bv.w, acc[i][3]);
        }
    }

    float4 b2v = *(const float4*)(sB2 + tc*4);
    #pragma unroll
    for (int i = 0; i < 8; i++) {
        int row = row0 + rb + i;
        if (row < NN) {
            float4 o;
            o.x = acc[i][0] + b2v.x;
            o.y = acc[i][1] + b2v.y;
            o.z = acc[i][2] + b2v.z;
            o.w = acc[i][3] + b2v.w;
            if (MODE == 1) {
                float4 tv = ((const float4*)R1)[row*32 + tc];
                float4 gv = ((const float4*)R2)[row*32 + tc];
                o.x = fmaxf(o.x + tv.x + gv.x, 0.f);
                o.y = fmaxf(o.y + tv.y + gv.y, 0.f);
                o.z = fmaxf(o.z + tv.z + gv.z, 0.f);
                o.w = fmaxf(o.w + tv.w + gv.w, 0.f);
            }
            if (MODE == 3) {
                o.x += sAT[(tc*4 + 0)*65 + rb + i];
                o.y += sAT[(tc*4 + 1)*65 + rb + i];
                o.z += sAT[(tc*4 + 2)*65 + rb + i];
                o.w += sAT[(tc*4 + 3)*65 + rb + i];
            }
            ((float4*)OUT)[(size_t)row*32 + tc] = o;
        }
    }
}

// ---------------- out branch: z = relu(t2@Wo+bo); t_out = t2 + LN(z) ----------------
#define SMEM_LN_FLOATS (16384 + 8320 + 8448 + 128 + 128 + 128)
#define SMEM_LN_BYTES  (SMEM_LN_FLOATS * 4)

__global__ __launch_bounds__(256, 1) void out_ln_kernel(
    const float* __restrict__ A,   // t2
    const float* __restrict__ W,  const float* __restrict__ B,
    const float* __restrict__ LG, const float* __restrict__ LB,
    float* __restrict__ OUT)
{
    extern __shared__ float sm[];
    float* sW  = sm;               // 16384
    float* sAT = sm + 16384;       // [128][65]
    float* sZ  = sAT + 8320;       // [64][132] row-major, padded
    float* sB  = sZ + 8448;
    float* sG  = sB + 128;
    float* sBe = sG + 128;

    const int tid = threadIdx.x;
    for (int i = tid; i < 16384; i += 256) sW[i] = W[i];
    if (tid < 128) { sB[tid] = B[tid]; sG[tid] = LG[tid]; sBe[tid] = LB[tid]; }

    const int row0 = blockIdx.x * TILE_R;
    for (int idx = tid; idx < TILE_R*128; idx += 256) {
        int r = idx >> 7, k = idx & 127;
        int row = row0 + r;
        sAT[k*65 + r] = (row < NN) ? A[(size_t)row*128 + k] : 0.f;
    }
    __syncthreads();

    const int tc = tid & 31;
    const int trg = tid >> 5;
    const int rb = trg * 8;

    float acc[8][4];
    #pragma unroll
    for (int i = 0; i < 8; i++)
        #pragma unroll
        for (int j = 0; j < 4; j++) acc[i][j] = 0.f;

    #pragma unroll 4
    for (int k = 0; k < 128; k++) {
        const float* ap = &sAT[k*65 + rb];
        float4 bv = *(const float4*)(sW + k*128 + tc*4);
        #pragma unroll
        for (int i = 0; i < 8; i++) {
            float a = ap[i];
            acc[i][0] = fmaf(a, bv.x, acc[i][0]);
            acc[i][1] = fmaf(a, bv.y, acc[i][1]);
            acc[i][2] = fmaf(a, bv.z, acc[i][2]);
            acc[i][3] = fmaf(a, bv.w, acc[i][3]);
        }
    }

    {   // bias + relu -> sZ (row-major for LN)
        float4 bv = *(const float4*)(sB + tc*4);
        #pragma unroll
        for (int i = 0; i < 8; i++) {
            float4 z;
            z.x = fmaxf(acc[i][0] + bv.x, 0.f);
            z.y = fmaxf(acc[i][1] + bv.y, 0.f);
            z.z = fmaxf(acc[i][2] + bv.z, 0.f);
            z.w = fmaxf(acc[i][3] + bv.w, 0.f);
            *(float4*)&sZ[(rb + i)*132 + tc*4] = z;
        }
    }
    __syncthreads();

    // LayerNorm: warp per row, 8 rows per warp
    for (int rr = 0; rr < 8; rr++) {
        int r = rr*8 + trg;
        int row = row0 + r;
        float4 z = *(const float4*)&sZ[r*132 + tc*4];
        float s  = z.x + z.y + z.z + z.w;
        float sq = z.x*z.x + z.y*z.y + z.z*z.z + z.w*z.w;
        #pragma unroll
        for (int d = 16; d > 0; d >>= 1) {
            s  += __shfl_xor_sync(0xffffffffu, s,  d);
            sq += __shfl_xor_sync(0xffffffffu, sq, d);
        }
        float m = s * (1.f/128.f);
        float var = sq * (1.f/128.f) - m*m;
        float rstd = rsqrtf(var + 1e-5f);
        if (row < NN) {
            float4 o;
            int c = tc*4;
            o.x = sAT[(c+0)*65 + r] + (z.x - m)*rstd*sG[c+0] + sBe[c+0];
            o.y = sAT[(c+1)*65 + r] + (z.y - m)*rstd*sG[c+1] + sBe[c+1];
            o.z = sAT[(c+2)*65 + r] + (z.z - m)*rstd*sG[c+2] + sBe[c+2];
            o.w = sAT[(c+3)*65 + r] + (z.w - m)*rstd*sG[c+3] + sBe[c+3];
            ((float4*)OUT)[(size_t)row*32 + tc] = o;
        }
    }
}

// ---------------- launcher ----------------
extern "C" void kernel_launch(void* const* d_in, const int* in_sizes, int n_in,
                              void* d_out, int out_size) {
    const float* x   = (const float*)d_in[0];
    const float* t   = (const float*)d_in[1];
    const int*   et  = (const int*)d_in[2];
    const int*   ex  = (const int*)d_in[3];
    const float* W1a = (const float*)d_in[4];
    const float* b1a = (const float*)d_in[5];
    const float* W2a = (const float*)d_in[6];
    const float* b2a = (const float*)d_in[7];
    const float* W1b = (const float*)d_in[8];
    const float* b1b = (const float*)d_in[9];
    const float* W2b = (const float*)d_in[10];
    const float* b2b = (const float*)d_in[11];
    const float* Wo  = (const float*)d_in[12];
    const float* bo  = (const float*)d_in[13];
    const float* lng = (const float*)d_in[14];
    const float* lnb = (const float*)d_in[15];
    const float* Wf1 = (const float*)d_in[16];
    const float* bf1 = (const float*)d_in[17];
    const float* Wf2 = (const float*)d_in[18];
    const float* bf2 = (const float*)d_in[19];
    float* out = (float*)d_out;

    float *pua, *pub, *pga, *pt2;
    cudaGetSymbolAddress((void**)&pua, g_ua);
    cudaGetSymbolAddress((void**)&pub, g_ub);
    cudaGetSymbolAddress((void**)&pga, g_ga);
    cudaGetSymbolAddress((void**)&pt2, g_t2);

    cudaFuncSetAttribute(mlp_kernel<0>, cudaFuncAttributeMaxDynamicSharedMemorySize, SMEM_MLP_BYTES);
    cudaFuncSetAttribute(mlp_kernel<1>, cudaFuncAttributeMaxDynamicSharedMemorySize, SMEM_MLP_BYTES);
    cudaFuncSetAttribute(mlp_kernel<3>, cudaFuncAttributeMaxDynamicSharedMemorySize, SMEM_MLP_BYTES);
    cudaFuncSetAttribute(out_ln_kernel, cudaFuncAttributeMaxDynamicSharedMemorySize, SMEM_LN_BYTES);

    // CSR build
    zero_cnt_kernel<<<(TWO_N + 1023)/1024, 1024>>>();
    hist_kernel<<<(EE + 255)/256, 256>>>(et, ex);
    scan1_kernel<<<NSB, SCAN_B>>>();
    scan2_kernel<<<1, 32>>>();
    scan3_kernel<<<(TWO_N + 1 + 255)/256, 256>>>();
    fill_kernel<<<(EE + 255)/256, 256>>>(et, ex);

    // aggregate: ua = t + sum t[src] (e_t), ub = t + sum x[src] (e_xct)
    agg_kernel<<<(NN + 7)/8, 256>>>(x, t, pua, pub);

    // gin_a = mlp_a(ua)
    mlp_kernel<0><<<NBLK, 256, SMEM_MLP_BYTES>>>(pua, W1a, b1a, W2a, b2a, nullptr, nullptr, pga);
    // t2 = relu(t + gin_a + mlp_b(ub))
    mlp_kernel<1><<<NBLK, 256, SMEM_MLP_BYTES>>>(pub, W1b, b1b, W2b, b2b, t, pga, pt2);
    // x_out = x + mlp_f(x)   -> first half of output
    mlp_kernel<3><<<NBLK, 256, SMEM_MLP_BYTES>>>(x, Wf1, bf1, Wf2, bf2, nullptr, nullptr, out);
    // t_out = t2 + LN(relu(t2@Wo+bo)) -> second half of output
    out_ln_kernel<<<NBLK, 256, SMEM_LN_BYTES>>>(pt2, Wo, bo, lng, lnb, out + (size_t)NN*DD);
}

// round 2
// speedup vs baseline: 1.0357x; 1.0357x over previous
#include <cuda_runtime.h>

typedef unsigned long long ull;

#define NN 50000
#define DD 128
#define EE 1600000
#define TWO_N (2*NN)
#define SCAN_B 512
#define NSB ((TWO_N + SCAN_B - 1)/SCAN_B)
#define TILE_R 64
#define NBLK ((NN + TILE_R - 1)/TILE_R)
#define PAD 68

// ---------------- f32x2 packed-math helpers (Blackwell) ----------------
__device__ __forceinline__ ull bcast2(float x) {
    ull r; asm("mov.b64 %0, {%1,%1};" : "=l"(r) : "f"(x)); return r;
}
__device__ __forceinline__ void ffma2(ull& d, ull a, ull b) {
    asm("fma.rn.f32x2 %0, %1, %2, %0;" : "+l"(d) : "l"(a), "l"(b));
}
__device__ __forceinline__ float2 unpack2(ull v) {
    float2 f; asm("mov.b64 {%0,%1}, %2;" : "=f"(f.x), "=f"(f.y) : "l"(v)); return f;
}

// ---------------- scratch (static device allocations) ----------------
__device__ int   g_cnt[TWO_N];        // degree, then fill-cursor
__device__ int   g_off[TWO_N + 1];    // CSR row offsets (set A rows 0..N-1, set B rows N..2N-1)
__device__ int   g_bsum[NSB];
__device__ int   g_col[2*EE];         // CSR column (src) indices
__device__ float g_ua[NN*DD];         // t + sum_{e_t} t[src]
__device__ float g_ub[NN*DD];         // t + sum_{e_xct} x[src]
__device__ float g_ga[NN*DD];         // gin_a output
__device__ float g_t2[NN*DD];         // relu(t + gin_a + gin_b)

// ---------------- CSR construction ----------------
__global__ void zero_cnt_kernel() {
    int i = blockIdx.x*blockDim.x + threadIdx.x;
    if (i < TWO_N) g_cnt[i] = 0;
}

__global__ void hist_kernel(const int* __restrict__ et, const int* __restrict__ ex) {
    int i = blockIdx.x*blockDim.x + threadIdx.x;
    if (i < EE) {
        atomicAdd(&g_cnt[et[EE + i]], 1);          // e_t dst
        atomicAdd(&g_cnt[NN + ex[EE + i]], 1);     // e_xct dst
    }
}

__global__ void scan1_kernel() {
    __shared__ int s[SCAN_B];
    int i = blockIdx.x*SCAN_B + threadIdx.x;
    int v = (i < TWO_N) ? g_cnt[i] : 0;
    s[threadIdx.x] = v;
    __syncthreads();
    #pragma unroll
    for (int d = 1; d < SCAN_B; d <<= 1) {
        int tv = (threadIdx.x >= d) ? s[threadIdx.x - d] : 0;
        __syncthreads();
        s[threadIdx.x] += tv;
        __syncthreads();
    }
    if (i < TWO_N) g_off[i + 1] = s[threadIdx.x];
    if (threadIdx.x == SCAN_B - 1) g_bsum[blockIdx.x] = s[SCAN_B - 1];
}

// parallel exclusive scan over NSB (<=256) block sums, single block
__global__ void scan2_kernel() {
    __shared__ int s[256];
    int v = (threadIdx.x < NSB) ? g_bsum[threadIdx.x] : 0;
    s[threadIdx.x] = v;
    __syncthreads();
    #pragma unroll
    for (int d = 1; d < 256; d <<= 1) {
        int tv = (threadIdx.x >= d) ? s[threadIdx.x - d] : 0;
        __syncthreads();
        s[threadIdx.x] += tv;
        __syncthreads();
    }
    if (threadIdx.x < NSB) g_bsum[threadIdx.x] = s[threadIdx.x] - v;  // exclusive
}

__global__ void scan3_kernel() {
    int i = blockIdx.x*blockDim.x + threadIdx.x;
    if (i == 0) { g_off[0] = 0; g_cnt[0] = 0; }
    else if (i <= TWO_N) {
        int v = g_off[i] + g_bsum[(i - 1) / SCAN_B];
        g_off[i] = v;
        if (i < TWO_N) g_cnt[i] = v;   // cursor = row start
    }
}

__global__ void fill_kernel(const int* __restrict__ et, const int* __restrict__ ex) {
    int i = blockIdx.x*blockDim.x + threadIdx.x;
    if (i < EE) {
        int p = atomicAdd(&g_cnt[et[EE + i]], 1);
        g_col[p] = et[i];
        int q = atomicAdd(&g_cnt[NN + ex[EE + i]], 1);
        g_col[q] = ex[i];
    }
}

// ---------------- aggregation: warp per destination node ----------------
__global__ void agg_kernel(const float* __restrict__ x, const float* __restrict__ t,
                           float* __restrict__ ua, float* __restrict__ ub) {
    int warp = (blockIdx.x*blockDim.x + threadIdx.x) >> 5;
    int lane = threadIdx.x & 31;
    if (warp >= NN) return;
    const float4* t4 = (const float4*)t;
    const float4* x4 = (const float4*)x;

    float4 base = t4[warp*32 + lane];
    float4 aA = base, aB = base;

    int e  = g_off[warp],      eE = g_off[warp + 1];
    for (; e + 1 < eE; e += 2) {
        int s0 = g_col[e], s1 = g_col[e + 1];
        float4 v0 = t4[s0*32 + lane];
        float4 v1 = t4[s1*32 + lane];
        aA.x += v0.x; aA.y += v0.y; aA.z += v0.z; aA.w += v0.w;
        aA.x += v1.x; aA.y += v1.y; aA.z += v1.z; aA.w += v1.w;
    }
    if (e < eE) {
        int s0 = g_col[e];
        float4 v0 = t4[s0*32 + lane];
        aA.x += v0.x; aA.y += v0.y; aA.z += v0.z; aA.w += v0.w;
    }

    e = g_off[NN + warp]; eE = g_off[NN + warp + 1];
    for (; e + 1 < eE; e += 2) {
        int s0 = g_col[e], s1 = g_col[e + 1];
        float4 v0 = x4[s0*32 + lane];
        float4 v1 = x4[s1*32 + lane];
        aB.x += v0.x; aB.y += v0.y; aB.z += v0.z; aB.w += v0.w;
        aB.x += v1.x; aB.y += v1.y; aB.z += v1.z; aB.w += v1.w;
    }
    if (e < eE) {
        int s0 = g_col[e];
        float4 v0 = x4[s0*32 + lane];
        aB.x += v0.x; aB.y += v0.y; aB.z += v0.z; aB.w += v0.w;
    }

    ((float4*)ua)[warp*32 + lane] = aA;
    ((float4*)ub)[warp*32 + lane] = aB;
}

// ---------------- packed GEMM micro-layer ----------------
// sIn: transposed tile [128][PAD] (feature k major, row minor).
// Each thread: 8 rows (as 4 b64 row-pairs) x 4 cols. acc[p][c] = pair of rows.
__device__ __forceinline__ void gemm_layer_f2(const float* __restrict__ sIn,
                                              const float* __restrict__ sW,
                                              int rb, int tc, ull acc[4][4]) {
    #pragma unroll 4
    for (int k = 0; k < 128; k++) {
        ulonglong2 A0 = *(const ulonglong2*)&sIn[k*PAD + rb];       // rows rb..rb+3
        ulonglong2 A1 = *(const ulonglong2*)&sIn[k*PAD + rb + 4];   // rows rb+4..rb+7
        float4 bv = *(const float4*)(sW + k*128 + tc*4);
        ull b0 = bcast2(bv.x), b1 = bcast2(bv.y), b2 = bcast2(bv.z), b3 = bcast2(bv.w);
        ull ap0 = A0.x, ap1 = A0.y, ap2 = A1.x, ap3 = A1.y;
        ffma2(acc[0][0], ap0, b0); ffma2(acc[0][1], ap0, b1); ffma2(acc[0][2], ap0, b2); ffma2(acc[0][3], ap0, b3);
        ffma2(acc[1][0], ap1, b0); ffma2(acc[1][1], ap1, b1); ffma2(acc[1][2], ap1, b2); ffma2(acc[1][3], ap1, b3);
        ffma2(acc[2][0], ap2, b0); ffma2(acc[2][1], ap2, b1); ffma2(acc[2][2], ap2, b2); ffma2(acc[2][3], ap2, b3);
        ffma2(acc[3][0], ap3, b0); ffma2(acc[3][1], ap3, b1); ffma2(acc[3][2], ap3, b2); ffma2(acc[3][3], ap3, b3);
    }
}

// ---------------- fused 2-layer MLP (both weights resident in smem) ----------------
// MODE 0: OUT = relu(A@W1+b1)@W2 + b2                  (gin_a)
// MODE 1: OUT = relu(R1 + R2 + mlp(A))                 (t2 from gin_b)
// MODE 3: OUT = A + mlp(A)                             (fc_x branch, residual from smem tile)
#define SMEM_MLP_FLOATS (16384 + 16384 + 128*PAD + 128*PAD + 128 + 128)
#define SMEM_MLP_BYTES  (SMEM_MLP_FLOATS * 4)

template<int MODE>
__global__ __launch_bounds__(256, 1) void mlp_kernel(
    const float* __restrict__ A,
    const float* __restrict__ W1, const float* __restrict__ B1,
    const float* __restrict__ W2, const float* __restrict__ B2,
    const float* __restrict__ R1, const float* __restrict__ R2,
    float* __restrict__ OUT)
{
    extern __shared__ float sm[];
    float* sW1 = sm;
    float* sW2 = sm + 16384;
    float* sAT = sm + 32768;              // [128][PAD] transposed
    float* sHT = sAT + 128*PAD;           // [128][PAD]
    float* sB1 = sHT + 128*PAD;
    float* sB2 = sB1 + 128;

    const int tid = threadIdx.x;
    for (int i = tid; i < 16384; i += 256) { sW1[i] = W1[i]; sW2[i] = W2[i]; }
    if (tid < 128) { sB1[tid] = B1[tid]; sB2[tid] = B2[tid]; }

    const int row0 = blockIdx.x * TILE_R;
    for (int idx = tid; idx < TILE_R*128; idx += 256) {
        int r = idx >> 7, k = idx & 127;
        int row = row0 + r;
        sAT[k*PAD + r] = (row < NN) ? A[(size_t)row*128 + k] : 0.f;
    }
    __syncthreads();

    const int tc = tid & 31;          // col group: cols tc*4..tc*4+3
    const int rb = (tid >> 5) * 8;    // row base within tile

    ull acc[4][4];
    #pragma unroll
    for (int p = 0; p < 4; p++)
        #pragma unroll
        for (int c = 0; c < 4; c++) acc[p][c] = 0ull;

    gemm_layer_f2(sAT, sW1, rb, tc, acc);

    {   // bias + relu -> transposed H tile
        float4 b1v = *(const float4*)(sB1 + tc*4);
        float bb[4] = {b1v.x, b1v.y, b1v.z, b1v.w};
        #pragma unroll
        for (int p = 0; p < 4; p++) {
            #pragma unroll
            for (int c = 0; c < 4; c++) {
                float2 v = unpack2(acc[p][c]);
                sHT[(tc*4 + c)*PAD + rb + 2*p]     = fmaxf(v.x + bb[c], 0.f);
                sHT[(tc*4 + c)*PAD + rb + 2*p + 1] = fmaxf(v.y + bb[c], 0.f);
            }
        }
    }
    __syncthreads();

    #pragma unroll
    for (int p = 0; p < 4; p++)
        #pragma unroll
        for (int c = 0; c < 4; c++) acc[p][c] = 0ull;

    gemm_layer_f2(sHT, sW2, rb, tc, acc);

    float4 b2v = *(const float4*)(sB2 + tc*4);
    #pragma unroll
    for (int p = 0; p < 4; p++) {
        float2 v0 = unpack2(acc[p][0]);
        float2 v1 = unpack2(acc[p][1]);
        float2 v2 = unpack2(acc[p][2]);
        float2 v3 = unpack2(acc[p][3]);
        #pragma unroll
        for (int q = 0; q < 2; q++) {
            int r = rb + 2*p + q;
            int row = row0 + r;
            if (row < NN) {
                float4 o;
                o.x = (q ? v0.y : v0.x) + b2v.x;
                o.y = (q ? v1.y : v1.x) + b2v.y;
                o.z = (q ? v2.y : v2.x) + b2v.z;
                o.w = (q ? v3.y : v3.x) + b2v.w;
                if (MODE == 1) {
                    float4 tv = ((const float4*)R1)[(size_t)row*32 + tc];
                    float4 gv = ((const float4*)R2)[(size_t)row*32 + tc];
                    o.x = fmaxf(o.x + tv.x + gv.x, 0.f);
                    o.y = fmaxf(o.y + tv.y + gv.y, 0.f);
                    o.z = fmaxf(o.z + tv.z + gv.z, 0.f);
                    o.w = fmaxf(o.w + tv.w + gv.w, 0.f);
                }
                if (MODE == 3) {
                    o.x += sAT[(tc*4 + 0)*PAD + r];
                    o.y += sAT[(tc*4 + 1)*PAD + r];
                    o.z += sAT[(tc*4 + 2)*PAD + r];
                    o.w += sAT[(tc*4 + 3)*PAD + r];
                }
                ((float4*)OUT)[(size_t)row*32 + tc] = o;
            }
        }
    }
}

// ---------------- out branch: z = relu(t2@Wo+bo); t_out = t2 + LN(z) ----------------
#define SMEM_LN_FLOATS (16384 + 128*PAD + 64*132 + 128 + 128 + 128)
#define SMEM_LN_BYTES  (SMEM_LN_FLOATS * 4)

__global__ __launch_bounds__(256, 1) void out_ln_kernel(
    const float* __restrict__ A,   // t2
    const float* __restrict__ W,  const float* __restrict__ B,
    const float* __restrict__ LG, const float* __restrict__ LB,
    float* __restrict__ OUT)
{
    extern __shared__ float sm[];
    float* sW  = sm;                    // 16384
    float* sAT = sm + 16384;            // [128][PAD]
    float* sZ  = sAT + 128*PAD;         // [64][132] row-major, padded
    float* sB  = sZ + 64*132;
    float* sG  = sB + 128;
    float* sBe = sG + 128;

    const int tid = threadIdx.x;
    for (int i = tid; i < 16384; i += 256) sW[i] = W[i];
    if (tid < 128) { sB[tid] = B[tid]; sG[tid] = LG[tid]; sBe[tid] = LB[tid]; }

    const int row0 = blockIdx.x * TILE_R;
    for (int idx = tid; idx < TILE_R*128; idx += 256) {
        int r = idx >> 7, k = idx & 127;
        int row = row0 + r;
        sAT[k*PAD + r] = (row < NN) ? A[(size_t)row*128 + k] : 0.f;
    }
    __syncthreads();

    const int tc  = tid & 31;
    const int trg = tid >> 5;
    const int rb  = trg * 8;

    ull acc[4][4];
    #pragma unroll
    for (int p = 0; p < 4; p++)
        #pragma unroll
        for (int c = 0; c < 4; c++) acc[p][c] = 0ull;

    gemm_layer_f2(sAT, sW, rb, tc, acc);

    {   // bias + relu -> sZ (row-major for LN)
        float4 bv = *(const float4*)(sB + tc*4);
        #pragma unroll
        for (int p = 0; p < 4; p++) {
            float2 v0 = unpack2(acc[p][0]);
            float2 v1 = unpack2(acc[p][1]);
            float2 v2 = unpack2(acc[p][2]);
            float2 v3 = unpack2(acc[p][3]);
            float4 zlo, zhi;
            zlo.x = fmaxf(v0.x + bv.x, 0.f); zhi.x = fmaxf(v0.y + bv.x, 0.f);
            zlo.y = fmaxf(v1.x + bv.y, 0.f); zhi.y = fmaxf(v1.y + bv.y, 0.f);
            zlo.z = fmaxf(v2.x + bv.z, 0.f); zhi.z = fmaxf(v2.y + bv.z, 0.f);
            zlo.w = fmaxf(v3.x + bv.w, 0.f); zhi.w = fmaxf(v3.y + bv.w, 0.f);
            *(float4*)&sZ[(rb + 2*p)*132 + tc*4]     = zlo;
            *(float4*)&sZ[(rb + 2*p + 1)*132 + tc*4] = zhi;
        }
    }
    __syncthreads();

    // LayerNorm: warp per row, 8 rows per warp
    for (int rr = 0; rr < 8; rr++) {
        int r = rr*8 + trg;
        int row = row0 + r;
        float4 z = *(const float4*)&sZ[r*132 + tc*4];
        float s  = z.x + z.y + z.z + z.w;
        float sq = z.x*z.x + z.y*z.y + z.z*z.z + z.w*z.w;
        #pragma unroll
        for (int d = 16; d > 0; d >>= 1) {
            s  += __shfl_xor_sync(0xffffffffu, s,  d);
            sq += __shfl_xor_sync(0xffffffffu, sq, d);
        }
        float m = s * (1.f/128.f);
        float var = sq * (1.f/128.f) - m*m;
        float rstd = rsqrtf(var + 1e-5f);
        if (row < NN) {
            float4 o;
            int c = tc*4;
            o.x = sAT[(c+0)*PAD + r] + (z.x - m)*rstd*sG[c+0] + sBe[c+0];
            o.y = sAT[(c+1)*PAD + r] + (z.y - m)*rstd*sG[c+1] + sBe[c+1];
            o.z = sAT[(c+2)*PAD + r] + (z.z - m)*rstd*sG[c+2] + sBe[c+2];
            o.w = sAT[(c+3)*PAD + r] + (z.w - m)*rstd*sG[c+3] + sBe[c+3];
            ((float4*)OUT)[(size_t)row*32 + tc] = o;
        }
    }
}

// ---------------- launcher ----------------
extern "C" void kernel_launch(void* const* d_in, const int* in_sizes, int n_in,
                              void* d_out, int out_size) {
    const float* x   = (const float*)d_in[0];
    const float* t   = (const float*)d_in[1];
    const int*   et  = (const int*)d_in[2];
    const int*   ex  = (const int*)d_in[3];
    const float* W1a = (const float*)d_in[4];
    const float* b1a = (const float*)d_in[5];
    const float* W2a = (const float*)d_in[6];
    const float* b2a = (const float*)d_in[7];
    const float* W1b = (const float*)d_in[8];
    const float* b1b = (const float*)d_in[9];
    const float* W2b = (const float*)d_in[10];
    const float* b2b = (const float*)d_in[11];
    const float* Wo  = (const float*)d_in[12];
    const float* bo  = (const float*)d_in[13];
    const float* lng = (const float*)d_in[14];
    const float* lnb = (const float*)d_in[15];
    const float* Wf1 = (const float*)d_in[16];
    const float* bf1 = (const float*)d_in[17];
    const float* Wf2 = (const float*)d_in[18];
    const float* bf2 = (const float*)d_in[19];
    float* out = (float*)d_out;

    float *pua, *pub, *pga, *pt2;
    cudaGetSymbolAddress((void**)&pua, g_ua);
    cudaGetSymbolAddress((void**)&pub, g_ub);
    cudaGetSymbolAddress((void**)&pga, g_ga);
    cudaGetSymbolAddress((void**)&pt2, g_t2);

    cudaFuncSetAttribute(mlp_kernel<0>, cudaFuncAttributeMaxDynamicSharedMemorySize, SMEM_MLP_BYTES);
    cudaFuncSetAttribute(mlp_kernel<1>, cudaFuncAttributeMaxDynamicSharedMemorySize, SMEM_MLP_BYTES);
    cudaFuncSetAttribute(mlp_kernel<3>, cudaFuncAttributeMaxDynamicSharedMemorySize, SMEM_MLP_BYTES);
    cudaFuncSetAttribute(out_ln_kernel, cudaFuncAttributeMaxDynamicSharedMemorySize, SMEM_LN_BYTES);

    // CSR build
    zero_cnt_kernel<<<(TWO_N + 1023)/1024, 1024>>>();
    hist_kernel<<<(EE + 255)/256, 256>>>(et, ex);
    scan1_kernel<<<NSB, SCAN_B>>>();
    scan2_kernel<<<1, 256>>>();
    scan3_kernel<<<(TWO_N + 1 + 255)/256, 256>>>();
    fill_kernel<<<(EE + 255)/256, 256>>>(et, ex);

    // aggregate: ua = t + sum t[src] (e_t), ub = t + sum x[src] (e_xct)
    agg_kernel<<<(NN + 7)/8, 256>>>(x, t, pua, pub);

    // gin_a = mlp_a(ua)
    mlp_kernel<0><<<NBLK, 256, SMEM_MLP_BYTES>>>(pua, W1a, b1a, W2a, b2a, nullptr, nullptr, pga);
    // t2 = relu(t + gin_a + mlp_b(ub))
    mlp_kernel<1><<<NBLK, 256, SMEM_MLP_BYTES>>>(pub, W1b, b1b, W2b, b2b, t, pga, pt2);
    // x_out = x + mlp_f(x)   -> first half of output
    mlp_kernel<3><<<NBLK, 256, SMEM_MLP_BYTES>>>(x, Wf1, bf1, Wf2, bf2, nullptr, nullptr, out);
    // t_out = t2 + LN(relu(t2@Wo+bo)) -> second half of output
    out_ln_kernel<<<NBLK, 256, SMEM_LN_BYTES>>>(pt2, Wo, bo, lng, lnb, out + (size_t)NN*DD);
}